// round 5
// baseline (speedup 1.0000x reference)
#include <cuda_runtime.h>

// Fixed shapes: preds/targets [32, 2048, 512] f32, lengths [32] i32.
#define BB 32
#define TT 2048
#define DD 512
#define G  1184      // grid = 148 SMs x 8 CTAs: exactly one wave
#define TARGET 1120  // target active chunks; C = sum(k_b) <= TARGET + BB <= G

// Scratch (device globals; every live slot rewritten each launch; counters
// wrap back to 0 -> graph-replay-safe, no init kernel).
__device__ float    g_S[G * DD];      // per-chunk diff-sum partials (2.4 MiB)
__device__ float    g_wordP[G];       // per-block word-loss partials
__device__ float    g_sentB[BB];      // per-b sentence term
__device__ unsigned g_ctrB[BB];       // per-b arrival counters (wrap at k_b)
__device__ unsigned g_ctr;            // global arrival counter (wrap at BB)

__device__ __forceinline__ float sl1(float d) {
    float ad = fabsf(d);
    return ad < 1.0f ? 0.5f * d * d : ad - 0.5f;
}

// One fused kernel, equal work per block. grid = G, block = 256
// (2 rows in flight x 128 float4 lanes covering D=512).
__global__ __launch_bounds__(256)
void k_fused(const float* __restrict__ preds,
             const float* __restrict__ targs,
             const int* __restrict__ lens,
             float* __restrict__ out) {
    const int g    = blockIdx.x;
    const int tid  = threadIdx.x;
    const int sub  = tid >> 7;           // 0/1: which row of the pair
    const int lane = tid & 127;
    const int dg   = lane << 2;          // float4 column group

    // ---- chunk table: k_b = max(1, floor(len_b * TARGET / R)) ----
    __shared__ int s_len[BB], s_k[BB], s_cc[BB + 1];
    if (tid == 0) {
        long R = 0;
        for (int i = 0; i < BB; i++) { s_len[i] = lens[i]; R += s_len[i]; }
        int acc = 0;
        for (int i = 0; i < BB; i++) {
            int k = (int)(((long)s_len[i] * TARGET) / R);
            if (k < 1) k = 1;
            s_k[i] = k;
            s_cc[i] = acc;
            acc += k;
        }
        s_cc[BB] = acc;
    }
    __syncthreads();
    const int C = s_cc[BB];

    if (g >= C) {                        // idle block (always same set per input)
        if (tid == 0) g_wordP[g] = 0.f;
        return;
    }

    // chunk -> (b, row range)
    int b = 0;
    while (g >= s_cc[b + 1]) b++;
    const int len = s_len[b];
    const int kb  = s_k[b];
    const int rpc = (len + kb - 1) / kb;            // rows per chunk (ceil)
    const int t0  = (g - s_cc[b]) * rpc;
    const int t1  = min(t0 + rpc, len);             // may be empty: handled

    // ---- Phase 1: stream this chunk's rows once (HBM-bound) ----
    float4 sd = make_float4(0.f, 0.f, 0.f, 0.f);
    float  w  = 0.f;
    const size_t base = (size_t)b * TT * DD + dg;

    #pragma unroll 4
    for (int t = t0 + sub; t < t1; t += 2) {
        const size_t off = base + (size_t)t * DD;
        const float4 pv = *reinterpret_cast<const float4*>(preds + off);
        const float4 tv = *reinterpret_cast<const float4*>(targs + off);
        float dx = pv.x - tv.x;
        float dy = pv.y - tv.y;
        float dz = pv.z - tv.z;
        float dw = pv.w - tv.w;
        sd.x += dx; sd.y += dy; sd.z += dz; sd.w += dw;
        w += sl1(dx) + sl1(dy) + sl1(dz) + sl1(dw);
    }

    // Combine sub0+sub1 diff-sums via shared; one slot per chunk.
    __shared__ float4 sh4[128];
    __shared__ float  sw[256];
    __shared__ bool   is_last_b, is_last_g;
    if (sub == 1) sh4[lane] = sd;
    sw[tid] = w;
    __syncthreads();
    if (sub == 0) {
        const float4 o = sh4[lane];
        sd.x += o.x; sd.y += o.y; sd.z += o.z; sd.w += o.w;
        *reinterpret_cast<float4*>(g_S + (size_t)g * DD + dg) = sd;
    }

    // Block-reduce the word partial.
    #pragma unroll
    for (int s = 128; s > 0; s >>= 1) {
        if (tid < s) sw[tid] += sw[tid + s];
        __syncthreads();
    }
    if (tid == 0) {
        g_wordP[g] = sw[0];
        __threadfence();
        // wraps to 0 after kb arrivals -> self-resetting across replays
        unsigned prev = atomicInc(&g_ctrB[b], (unsigned)(kb - 1));
        is_last_b = (prev == (unsigned)(kb - 1));
    }
    __syncthreads();
    if (!is_last_b) return;

    // ---- Phase 2 (last chunk of this b): fold kb slots, L2-hot ----
    __threadfence();   // acquire: see all kb chunks' g_S writes

    float4 s4 = make_float4(0.f, 0.f, 0.f, 0.f);
    const int c0 = s_cc[b];
    for (int j = sub; j < kb; j += 2) {
        const float4 v = *reinterpret_cast<const float4*>(
            g_S + (size_t)(c0 + j) * DD + dg);
        s4.x += v.x; s4.y += v.y; s4.z += v.z; s4.w += v.w;
    }
    __syncthreads();   // sh4 reuse
    if (sub == 1) sh4[lane] = s4;
    __syncthreads();
    float wsent = 0.f;
    if (sub == 0) {
        const float4 o = sh4[lane];
        s4.x += o.x; s4.y += o.y; s4.z += o.z; s4.w += o.w;
        const float invlen = 1.0f / (float)len;
        wsent = sl1(s4.x * invlen) + sl1(s4.y * invlen)
              + sl1(s4.z * invlen) + sl1(s4.w * invlen);
    }
    sw[tid] = wsent;
    __syncthreads();
    #pragma unroll
    for (int s = 128; s > 0; s >>= 1) {
        if (tid < s) sw[tid] += sw[tid + s];
        __syncthreads();
    }
    if (tid == 0) {
        g_sentB[b] = sw[0] * (1.0f / (float)DD);
        __threadfence();
        unsigned prev = atomicInc(&g_ctr, BB - 1u);
        is_last_g = (prev == BB - 1u);
    }
    __syncthreads();
    if (!is_last_g) return;

    // ---- Phase 3 (single final block): scalar combine, L2-hot ----
    __threadfence();

    float wsum = 0.f;
    #pragma unroll
    for (int i = tid; i < G; i += 256) wsum += g_wordP[i];
    float ssum = 0.f;
    int   lsum = 0;
    if (tid < BB) { ssum = g_sentB[tid]; lsum = s_len[tid]; }

    __shared__ float swd[256];
    __shared__ float ssn[256];
    __shared__ int   sln[256];
    swd[tid] = wsum; ssn[tid] = ssum; sln[tid] = lsum;
    __syncthreads();
    #pragma unroll
    for (int s = 128; s > 0; s >>= 1) {
        if (tid < s) {
            swd[tid] += swd[tid + s];
            ssn[tid] += ssn[tid + s];
            sln[tid] += sln[tid + s];
        }
        __syncthreads();
    }
    if (tid == 0) {
        const float n_valid = (float)sln[0] * (float)DD;   // <= 2^25, exact
        out[0] = swd[0] / n_valid + ssn[0] * (1.0f / (float)BB);
    }
}

extern "C" void kernel_launch(void* const* d_in, const int* in_sizes, int n_in,
                              void* d_out, int out_size) {
    const float* preds = (const float*)d_in[0];
    const float* targs = (const float*)d_in[1];
    const int*   lens  = (const int*)d_in[2];
    float* out = (float*)d_out;

    k_fused<<<G, 256>>>(preds, targs, lens, out);
}

// round 6
// speedup vs baseline: 1.0928x; 1.0928x over previous
#include <cuda_runtime.h>

// Fixed shapes: preds/targets [32, 2048, 512] f32, lengths [32] i32.
#define BB 32
#define TT 2048
#define DD 512
#define G  1184      // grid = 148 SMs x 8 CTAs: exactly one wave at 32 regs
#define TARGET 1120  // C = sum(k_b) <= TARGET + BB = 1152 <= G

// Scratch (device globals; every live slot rewritten each launch; counters
// wrap back to 0 -> graph-replay-safe, no init kernel).
__device__ float    g_S[G * DD];      // per-chunk diff-sum partials (2.4 MiB)
__device__ float    g_wordP[G];       // per-chunk word-loss partials
__device__ float    g_sentB[BB];      // per-b sentence term
__device__ unsigned g_ctrB[BB];       // per-b arrival counters (wrap at k_b)
__device__ unsigned g_ctr;            // global arrival counter (wrap at BB)

__device__ __forceinline__ float sl1(float d) {
    float ad = fabsf(d);
    return ad < 1.0f ? 0.5f * d * d : ad - 0.5f;
}

// One fused kernel, equal work per block, ONE wave. grid = G, block = 256
// (2 rows in flight x 128 float4 lanes covering D=512).
__global__ __launch_bounds__(256, 8)   // force <=32 regs: 8 CTAs/SM
void k_fused(const float* __restrict__ preds,
             const float* __restrict__ targs,
             const int* __restrict__ lens,
             float* __restrict__ out) {
    const int g    = blockIdx.x;
    const int tid  = threadIdx.x;
    const int sub  = tid >> 7;           // 0/1: which row of the pair
    const int lane = tid & 127;
    const int dg   = lane << 2;          // float4 column group

    // ---- chunk table via warp scan (warp 0): k_b = max(1, floor(len_b*TARGET/R)) ----
    __shared__ int s_len[BB], s_k[BB], s_cc[BB + 1];
    if (tid < 32) {
        const int len = lens[tid];
        s_len[tid] = len;
        int R = len;
        #pragma unroll
        for (int o = 16; o; o >>= 1) R += __shfl_xor_sync(0xffffffffu, R, o);
        int k = (int)(((long)len * TARGET) / (long)R);
        if (k < 1) k = 1;
        s_k[tid] = k;
        int x = k;                       // inclusive prefix scan
        #pragma unroll
        for (int o = 1; o < 32; o <<= 1) {
            int y = __shfl_up_sync(0xffffffffu, x, o);
            if (tid >= o) x += y;
        }
        s_cc[tid] = x - k;               // exclusive
        if (tid == 31) s_cc[32] = x;
    }
    __syncthreads();
    const int C = s_cc[BB];

    if (g >= C) return;                  // idle block (same set every replay)

    // chunk -> (b, row range)
    int b = 0;
    while (g >= s_cc[b + 1]) b++;
    const int len = s_len[b];
    const int kb  = s_k[b];
    const int rpc = (len + kb - 1) / kb;            // rows per chunk (ceil)
    const int t0  = (g - s_cc[b]) * rpc;
    const int t1  = min(t0 + rpc, len);             // may be empty; fine

    // ---- Phase 1: stream this chunk's rows once (HBM-bound) ----
    float4 sd = make_float4(0.f, 0.f, 0.f, 0.f);
    float  w  = 0.f;
    const size_t base = (size_t)b * TT * DD + dg;

    #pragma unroll 4
    for (int t = t0 + sub; t < t1; t += 2) {
        const size_t off = base + (size_t)t * DD;
        const float4 pv = *reinterpret_cast<const float4*>(preds + off);
        const float4 tv = *reinterpret_cast<const float4*>(targs + off);
        float dx = pv.x - tv.x;
        float dy = pv.y - tv.y;
        float dz = pv.z - tv.z;
        float dw = pv.w - tv.w;
        sd.x += dx; sd.y += dy; sd.z += dz; sd.w += dw;
        w += sl1(dx) + sl1(dy) + sl1(dz) + sl1(dw);
    }

    // Combine sub0+sub1 diff-sums via shared; one slot per chunk.
    __shared__ float4 sh4[128];
    __shared__ float  sw[256];
    __shared__ bool   is_last_b, is_last_g;
    if (sub == 1) sh4[lane] = sd;
    sw[tid] = w;
    __syncthreads();
    if (sub == 0) {
        const float4 o = sh4[lane];
        sd.x += o.x; sd.y += o.y; sd.z += o.z; sd.w += o.w;
        *reinterpret_cast<float4*>(g_S + (size_t)g * DD + dg) = sd;
    }

    // Block-reduce the word partial.
    #pragma unroll
    for (int s = 128; s > 0; s >>= 1) {
        if (tid < s) sw[tid] += sw[tid + s];
        __syncthreads();
    }
    if (tid == 0) {
        g_wordP[g] = sw[0];
        __threadfence();
        // wraps to 0 after kb arrivals -> self-resetting across replays
        unsigned prev = atomicInc(&g_ctrB[b], (unsigned)(kb - 1));
        is_last_b = (prev == (unsigned)(kb - 1));
    }
    __syncthreads();
    if (!is_last_b) return;

    // ---- Phase 2 (last chunk of this b): fold kb slots, L2-hot ----
    __threadfence();   // acquire: see all kb chunks' g_S writes

    float4 s4 = make_float4(0.f, 0.f, 0.f, 0.f);
    const int c0 = s_cc[b];
    for (int j = sub; j < kb; j += 2) {
        const float4 v = *reinterpret_cast<const float4*>(
            g_S + (size_t)(c0 + j) * DD + dg);
        s4.x += v.x; s4.y += v.y; s4.z += v.z; s4.w += v.w;
    }
    __syncthreads();   // sh4 reuse
    if (sub == 1) sh4[lane] = s4;
    __syncthreads();
    float wsent = 0.f;
    if (sub == 0) {
        const float4 o = sh4[lane];
        s4.x += o.x; s4.y += o.y; s4.z += o.z; s4.w += o.w;
        const float invlen = 1.0f / (float)len;
        wsent = sl1(s4.x * invlen) + sl1(s4.y * invlen)
              + sl1(s4.z * invlen) + sl1(s4.w * invlen);
    }
    sw[tid] = wsent;
    __syncthreads();
    #pragma unroll
    for (int s = 128; s > 0; s >>= 1) {
        if (tid < s) sw[tid] += sw[tid + s];
        __syncthreads();
    }
    if (tid == 0) {
        g_sentB[b] = sw[0] * (1.0f / (float)DD);
        __threadfence();
        unsigned prev = atomicInc(&g_ctr, BB - 1u);
        is_last_g = (prev == BB - 1u);
    }
    __syncthreads();
    if (!is_last_g) return;

    // ---- Phase 3 (single final block): scalar combine, L2-hot ----
    __threadfence();

    float wsum = 0.f;
    for (int i = tid; i < C; i += 256) wsum += g_wordP[i];
    float ssum = 0.f;
    int   lsum = 0;
    if (tid < BB) { ssum = g_sentB[tid]; lsum = s_len[tid]; }

    __shared__ float swd[256];
    __shared__ float ssn[256];
    __shared__ int   sln[256];
    swd[tid] = wsum; ssn[tid] = ssum; sln[tid] = lsum;
    __syncthreads();
    #pragma unroll
    for (int s = 128; s > 0; s >>= 1) {
        if (tid < s) {
            swd[tid] += swd[tid + s];
            ssn[tid] += ssn[tid + s];
            sln[tid] += sln[tid + s];
        }
        __syncthreads();
    }
    if (tid == 0) {
        const float n_valid = (float)sln[0] * (float)DD;   // <= 2^25, exact
        out[0] = swd[0] / n_valid + ssn[0] * (1.0f / (float)BB);
    }
}

extern "C" void kernel_launch(void* const* d_in, const int* in_sizes, int n_in,
                              void* d_out, int out_size) {
    const float* preds = (const float*)d_in[0];
    const float* targs = (const float*)d_in[1];
    const int*   lens  = (const int*)d_in[2];
    float* out = (float*)d_out;

    k_fused<<<G, 256>>>(preds, targs, lens, out);
}

// round 7
// speedup vs baseline: 1.3333x; 1.2201x over previous
#include <cuda_runtime.h>

// Fixed shapes: preds/targets [32, 2048, 512] f32, lengths [32] i32.
#define BB 32
#define TT 2048
#define DD 512
#define TILES 64   // blocks (t-tiles) per batch row, strided t assignment

// Scratch (device globals; every slot rewritten each launch; counters wrap
// back to 0 -> graph-replay-safe, no init kernel).
__device__ float    g_S[BB * TILES * DD];   // per-(b,tile,d) diff-sum partials, 4 MiB
__device__ float    g_wordP[BB * TILES];    // per-block word-loss partials (2048)
__device__ float    g_sentB[BB];            // per-b sentence term
__device__ unsigned g_ctrB[BB];             // per-b arrival counters (wrap at TILES-1)
__device__ unsigned g_ctr;                  // global arrival counter (wrap at BB-1)

__device__ __forceinline__ float sl1(float d) {
    float ad = fabsf(d);
    return ad < 1.0f ? 0.5f * d * d : ad - 0.5f;
}

// One fused kernel. grid = (TILES, BB), block = 256 (2 t-rows x 128 float4 lanes).
__global__ __launch_bounds__(256)
void k_fused(const float* __restrict__ preds,
             const float* __restrict__ targs,
             const int* __restrict__ lens,
             float* __restrict__ out) {
    const int b    = blockIdx.y;
    const int tile = blockIdx.x;
    const int tid  = threadIdx.x;
    const int sub  = tid >> 7;            // 0/1: which row of the pair
    const int lane = tid & 127;
    const int dg   = lane << 2;           // float4 column group (covers D=512)

    const int len = lens[b];

    // ---- Phase 1: stream valid rows once (HBM-bound), streaming loads ----
    float4 sd0 = make_float4(0.f, 0.f, 0.f, 0.f);
    float4 sd1 = make_float4(0.f, 0.f, 0.f, 0.f);
    float  w0 = 0.f, w1 = 0.f;

    const float* pbase = preds + (size_t)b * TT * DD + dg;
    const float* qbase = targs + (size_t)b * TT * DD + dg;
    const int step = 2 * TILES;           // 128 rows between this thread's rows

    int t = tile + sub * TILES;
    // paired main loop: 4 independent LDG.128 (evict-first) per iteration
    for (; t + step < len; t += 2 * step) {
        const size_t o0 = (size_t)t * DD;
        const size_t o1 = (size_t)(t + step) * DD;
        const float4 p0 = __ldcs(reinterpret_cast<const float4*>(pbase + o0));
        const float4 q0 = __ldcs(reinterpret_cast<const float4*>(qbase + o0));
        const float4 p1 = __ldcs(reinterpret_cast<const float4*>(pbase + o1));
        const float4 q1 = __ldcs(reinterpret_cast<const float4*>(qbase + o1));

        float ax = p0.x - q0.x, ay = p0.y - q0.y, az = p0.z - q0.z, aw = p0.w - q0.w;
        sd0.x += ax; sd0.y += ay; sd0.z += az; sd0.w += aw;
        w0 += sl1(ax) + sl1(ay) + sl1(az) + sl1(aw);

        float bx = p1.x - q1.x, by = p1.y - q1.y, bz = p1.z - q1.z, bw = p1.w - q1.w;
        sd1.x += bx; sd1.y += by; sd1.z += bz; sd1.w += bw;
        w1 += sl1(bx) + sl1(by) + sl1(bz) + sl1(bw);
    }
    if (t < len) {                        // at most one leftover row
        const size_t o0 = (size_t)t * DD;
        const float4 p0 = __ldcs(reinterpret_cast<const float4*>(pbase + o0));
        const float4 q0 = __ldcs(reinterpret_cast<const float4*>(qbase + o0));
        float ax = p0.x - q0.x, ay = p0.y - q0.y, az = p0.z - q0.z, aw = p0.w - q0.w;
        sd0.x += ax; sd0.y += ay; sd0.z += az; sd0.w += aw;
        w0 += sl1(ax) + sl1(ay) + sl1(az) + sl1(aw);
    }
    float4 sd = make_float4(sd0.x + sd1.x, sd0.y + sd1.y,
                            sd0.z + sd1.z, sd0.w + sd1.w);
    float w = w0 + w1;

    // Combine sub0+sub1 diff-sums via shared; one slot per (b,tile).
    __shared__ float4 sh4[128];
    __shared__ float  sw[256];
    __shared__ bool   is_last_b, is_last_g;
    if (sub == 1) sh4[lane] = sd;
    sw[tid] = w;
    __syncthreads();
    if (sub == 0) {
        const float4 o = sh4[lane];
        sd.x += o.x; sd.y += o.y; sd.z += o.z; sd.w += o.w;
        __stcs(reinterpret_cast<float4*>(g_S + ((size_t)(b * TILES + tile)) * DD + dg), sd);
    }

    // Block-reduce the word partial.
    #pragma unroll
    for (int s = 128; s > 0; s >>= 1) {
        if (tid < s) sw[tid] += sw[tid + s];
        __syncthreads();
    }
    if (tid == 0) {
        g_wordP[b * TILES + tile] = sw[0];
        __threadfence();
        // wraps to 0 after TILES arrivals -> self-resetting across replays
        unsigned prev = atomicInc(&g_ctrB[b], TILES - 1u);
        is_last_b = (prev == TILES - 1u);
    }
    __syncthreads();
    if (!is_last_b) return;

    // ---- Phase 2 (last block of this b): fold 64 partial slots, L2-hot ----
    __threadfence();  // acquire: see all 64 blocks' g_S writes for this b

    float4 s4 = make_float4(0.f, 0.f, 0.f, 0.f);
    const float* Sb = g_S + (size_t)b * TILES * DD;
    #pragma unroll
    for (int j = sub * (TILES / 2); j < (sub + 1) * (TILES / 2); j++) {
        const float4 v = *reinterpret_cast<const float4*>(Sb + (size_t)j * DD + dg);
        s4.x += v.x; s4.y += v.y; s4.z += v.z; s4.w += v.w;
    }
    __syncthreads();   // sh4 reuse
    if (sub == 1) sh4[lane] = s4;
    __syncthreads();
    float wsent = 0.f;
    if (sub == 0) {
        const float4 o = sh4[lane];
        s4.x += o.x; s4.y += o.y; s4.z += o.z; s4.w += o.w;
        const float invlen = 1.0f / (float)len;
        wsent = sl1(s4.x * invlen) + sl1(s4.y * invlen)
              + sl1(s4.z * invlen) + sl1(s4.w * invlen);
    }
    sw[tid] = wsent;
    __syncthreads();
    #pragma unroll
    for (int s = 128; s > 0; s >>= 1) {
        if (tid < s) sw[tid] += sw[tid + s];
        __syncthreads();
    }
    if (tid == 0) {
        g_sentB[b] = sw[0] * (1.0f / (float)DD);
        __threadfence();
        unsigned prev = atomicInc(&g_ctr, BB - 1u);
        is_last_g = (prev == BB - 1u);
    }
    __syncthreads();
    if (!is_last_g) return;

    // ---- Phase 3 (single final block): scalar combine, L2-hot ----
    __threadfence();

    float wsum = 0.f;
    #pragma unroll
    for (int i = tid; i < BB * TILES; i += 256) wsum += g_wordP[i];
    float ssum = 0.f;
    int   lsum = 0;
    if (tid < BB) { ssum = g_sentB[tid]; lsum = lens[tid]; }

    __shared__ float swd[256];
    __shared__ float ssn[256];
    __shared__ int   sln[256];
    swd[tid] = wsum; ssn[tid] = ssum; sln[tid] = lsum;
    __syncthreads();
    #pragma unroll
    for (int s = 128; s > 0; s >>= 1) {
        if (tid < s) {
            swd[tid] += swd[tid + s];
            ssn[tid] += ssn[tid + s];
            sln[tid] += sln[tid + s];
        }
        __syncthreads();
    }
    if (tid == 0) {
        const float n_valid = (float)sln[0] * (float)DD;  // <= 2^25, exact
        out[0] = swd[0] / n_valid + ssn[0] * (1.0f / (float)BB);
    }
}

extern "C" void kernel_launch(void* const* d_in, const int* in_sizes, int n_in,
                              void* d_out, int out_size) {
    const float* preds = (const float*)d_in[0];
    const float* targs = (const float*)d_in[1];
    const int*   lens  = (const int*)d_in[2];
    float* out = (float*)d_out;

    k_fused<<<dim3(TILES, BB), 256>>>(preds, targs, lens, out);
}